// round 6
// baseline (speedup 1.0000x reference)
#include <cuda_runtime.h>
#include <cuda_fp16.h>
#include <cstdint>
#include <cstddef>

#define DI __device__ __forceinline__

static constexpr int M_TOT = 8192, N_TOT = 4096, K_TOT = 4096;
static constexpr int BM = 128, BN = 256, BK = 64;
static constexpr int NSTG = 3;
static constexpr int NK = K_TOT / BK;                 // 64 chunks

static constexpr int A_STG = BM * 128;                // 16384 B (128B rows of 64 halfs)
static constexpr int B_STG = BN * 128;                // 32768 B
static constexpr int STAGE_BYTES = A_STG + B_STG;     // 49152 B
static constexpr int SM_BIAS = 0;                     // 256 floats
static constexpr int SM_STAGE = 1024;
static constexpr int SMEM_TOTAL = SM_STAGE + NSTG * STAGE_BYTES;  // 148480

// scratch (allocation-free rule: __device__ globals)
__device__ uint4 g_x16_v[(size_t)M_TOT * K_TOT / 8];   // 64 MB fp16 x
__device__ uint4 g_w16_v[(size_t)N_TOT * K_TOT / 8];   // 32 MB fp16 W

// ------------------------- PTX helpers (sm_80+ baseline only) -------------------------
DI uint32_t smem_u32(const void* p) {
    uint32_t a;
    asm("{.reg .u64 t; cvta.to.shared.u64 t, %1; cvt.u32.u64 %0, t;}" : "=r"(a) : "l"(p));
    return a;
}
DI void cp16(uint32_t dst, const void* src) {
    asm volatile("cp.async.cg.shared.global [%0], [%1], 16;" :: "r"(dst), "l"(src));
}
DI void cp_commit() { asm volatile("cp.async.commit_group;" ::: "memory"); }
template <int N> DI void cp_wait() { asm volatile("cp.async.wait_group %0;" :: "n"(N) : "memory"); }

DI void ldsm_x4(uint32_t& r0, uint32_t& r1, uint32_t& r2, uint32_t& r3, uint32_t a) {
    asm volatile("ldmatrix.sync.aligned.m8n8.x4.shared.b16 {%0,%1,%2,%3}, [%4];"
                 : "=r"(r0), "=r"(r1), "=r"(r2), "=r"(r3) : "r"(a));
}
DI void mma16816(float* c, uint32_t a0, uint32_t a1, uint32_t a2, uint32_t a3,
                 uint32_t b0, uint32_t b1) {
    asm volatile(
        "mma.sync.aligned.m16n8k16.row.col.f32.f16.f16.f32 "
        "{%0,%1,%2,%3}, {%4,%5,%6,%7}, {%8,%9}, {%0,%1,%2,%3};"
        : "+f"(c[0]), "+f"(c[1]), "+f"(c[2]), "+f"(c[3])
        : "r"(a0), "r"(a1), "r"(a2), "r"(a3), "r"(b0), "r"(b1));
}
#define SWZ(row, colbyte) ((uint32_t)(colbyte) ^ (((uint32_t)(row) & 7u) << 4))

// ------------------------- pre-kernel 1: x fp32 -> fp16 -------------------------
__global__ void __launch_bounds__(256) cvt_x_kernel(const float4* __restrict__ x) {
    size_t i = (size_t)blockIdx.x * 256 + threadIdx.x;   // 8 floats per thread
    float4 a = x[2 * i], b = x[2 * i + 1];
    __half2* o = (__half2*)g_x16_v;
    o[4 * i + 0] = __floats2half2_rn(a.x, a.y);
    o[4 * i + 1] = __floats2half2_rn(a.z, a.w);
    o[4 * i + 2] = __floats2half2_rn(b.x, b.y);
    o[4 * i + 3] = __floats2half2_rn(b.z, b.w);
}

// ------------------------- pre-kernel 2: fp4 dequant -> fp16 W -------------------------
DI float fp4_val(uint32_t n) {
    uint32_t s = (n >> 3) & 1, e = (n >> 1) & 3, m = n & 1;
    uint32_t bits = e ? (((e + 126u) << 23) | (m << 22)) : (m ? 0x3F000000u : 0u);
    bits |= s << 31;
    return __uint_as_float(bits);
}

__global__ void __launch_bounds__(256) deq_w_kernel(const int* __restrict__ wd,
                                                    const int* __restrict__ ws,
                                                    const float* __restrict__ g) {
    int row = blockIdx.x;        // output row 0..4095
    int grp = threadIdx.x;       // scale group 0..255 (16 input cols each)
    float gl = *g;
    int code = ws[row * 256 + grp];            // e4m3 code
    int e = (code >> 3) & 0xF, mm = code & 7;
    float sc = e ? __uint_as_float(((uint32_t)(e + 120) << 23) | ((uint32_t)mm << 20))
                 : (float)mm * 0.001953125f;   // m * 2^-9 (subnormal)
    if (code & 0x80) sc = -sc;
    sc *= gl;

    const int4* src = (const int4*)(wd + (size_t)row * 2048 + grp * 8);
    int4 p0 = src[0], p1 = src[1];
    int v[8] = {p0.x, p0.y, p0.z, p0.w, p1.x, p1.y, p1.z, p1.w};
    __half2 o[8];
#pragma unroll
    for (int j = 0; j < 8; ++j) {
        uint32_t b = (uint32_t)v[j];
        o[j] = __floats2half2_rn(fp4_val(b & 0xF) * sc, fp4_val((b >> 4) & 0xF) * sc);
    }
    uint4* dst = (uint4*)((half*)g_w16_v + (size_t)row * 4096 + grp * 16);
    dst[0] = ((const uint4*)o)[0];
    dst[1] = ((const uint4*)o)[1];
}

// ------------------------- GEMM: mma.sync f16, 128x256 tile, 3-stage cp.async ----------
__global__ void __launch_bounds__(256, 1) gemm_kernel(const float* __restrict__ bias,
                                                      float* __restrict__ out) {
    extern __shared__ char smem[];
    const uint32_t sb = smem_u32(smem);
    const int tid = threadIdx.x, wid = tid >> 5, lane = tid & 31;
    const int wm = wid >> 2;          // 0..1  -> 64-row band
    const int wn = wid & 3;           // 0..3  -> 64-col band
    const int n0 = blockIdx.x * BN;
    const int m0 = blockIdx.y * BM;
    const half* X = (const half*)g_x16_v;
    const half* Wm = (const half*)g_w16_v;

    ((float*)(smem + SM_BIAS))[tid] = bias[n0 + tid];

    // stage loader: A rows = x[m0..+128], B rows = W[n0..+256]; 128B (64 half) rows, XOR swizzle
    auto load_stage = [&](int chunk) {
        const uint32_t st = sb + SM_STAGE + (uint32_t)(chunk % NSTG) * STAGE_BYTES;
        const int kc = chunk * BK;
#pragma unroll
        for (int j = 0; j < 4; ++j) {                 // A: 1024 chunks of 16B
            int c = tid + 256 * j;
            int row = c >> 3, col = c & 7;
            uint32_t dst = st + (uint32_t)row * 128 + SWZ(row, col * 16);
            cp16(dst, X + (size_t)(m0 + row) * K_TOT + kc + col * 8);
        }
#pragma unroll
        for (int j = 0; j < 8; ++j) {                 // B: 2048 chunks of 16B
            int c = tid + 256 * j;
            int row = c >> 3, col = c & 7;
            uint32_t dst = st + (uint32_t)A_STG + (uint32_t)row * 128 + SWZ(row, col * 16);
            cp16(dst, Wm + (size_t)(n0 + row) * K_TOT + kc + col * 8);
        }
    };

    for (int c = 0; c < NSTG - 1; ++c) { load_stage(c); cp_commit(); }

    float acc[4][8][4];
#pragma unroll
    for (int mi = 0; mi < 4; ++mi)
#pragma unroll
        for (int ni = 0; ni < 8; ++ni)
#pragma unroll
            for (int q = 0; q < 4; ++q) acc[mi][ni][q] = 0.f;

#pragma unroll 1
    for (int ki = 0; ki < NK; ++ki) {
        cp_wait<NSTG - 2>();
        __syncthreads();
        if (ki + NSTG - 1 < NK) load_stage(ki + NSTG - 1);
        cp_commit();

        const uint32_t st = sb + SM_STAGE + (uint32_t)(ki % NSTG) * STAGE_BYTES;
        const uint32_t aS = st, bS = st + A_STG;
#pragma unroll
        for (int ks = 0; ks < 4; ++ks) {
            const int k0 = ks * 16;                    // halfs
            uint32_t af[4][4];
#pragma unroll
            for (int mi = 0; mi < 4; ++mi) {           // A frags: ldmatrix.x4 (rows = m)
                int row = wm * 64 + mi * 16 + (lane & 15);
                int colb = (k0 + ((lane >> 4) << 3)) * 2;
                ldsm_x4(af[mi][0], af[mi][1], af[mi][2], af[mi][3],
                        aS + (uint32_t)row * 128 + SWZ(row, colb));
            }
            uint32_t bf[8][2];
#pragma unroll
            for (int p = 0; p < 4; ++p) {              // B frags: NON-trans ldmatrix (rows = n)
                // matrices: (n0-7,k0-7)->b0 of ni=2p; (n0-7,k8-15)->b1; (n8-15,k0-7)->b0 of 2p+1; (n8-15,k8-15)->b1
                int row = wn * 64 + p * 16 + ((lane >> 4) << 3) + (lane & 7);
                int colb = (k0 + (((lane >> 3) & 1) << 3)) * 2;
                ldsm_x4(bf[2 * p][0], bf[2 * p][1], bf[2 * p + 1][0], bf[2 * p + 1][1],
                        bS + (uint32_t)row * 128 + SWZ(row, colb));
            }
#pragma unroll
            for (int mi = 0; mi < 4; ++mi)
#pragma unroll
                for (int ni = 0; ni < 8; ++ni)
                    mma16816(acc[mi][ni], af[mi][0], af[mi][1], af[mi][2], af[mi][3],
                             bf[ni][0], bf[ni][1]);
        }
    }
    cp_wait<0>();

    // epilogue: D m16n8 frag layout -> global + bias
    const float* sbias = (const float*)(smem + SM_BIAS);
#pragma unroll
    for (int mi = 0; mi < 4; ++mi) {
        int mr = m0 + wm * 64 + mi * 16 + (lane >> 2);
        float* o0 = out + (size_t)mr * N_TOT;
        float* o1 = out + (size_t)(mr + 8) * N_TOT;
#pragma unroll
        for (int ni = 0; ni < 8; ++ni) {
            int nc = wn * 64 + ni * 8 + (lane & 3) * 2;
            float b0 = sbias[nc], b1 = sbias[nc + 1];
            int ng = n0 + nc;
            *(float2*)(o0 + ng) = make_float2(acc[mi][ni][0] + b0, acc[mi][ni][1] + b1);
            *(float2*)(o1 + ng) = make_float2(acc[mi][ni][2] + b0, acc[mi][ni][3] + b1);
        }
    }
}

// ------------------------- launch -------------------------
extern "C" void kernel_launch(void* const* d_in, const int* in_sizes, int n_in,
                              void* d_out, int out_size) {
    const float* x  = (const float*)d_in[0];
    const int* wd   = (const int*)d_in[1];
    const int* ws   = (const int*)d_in[2];
    const float* g  = (const float*)d_in[3];
    const float* bias = (const float*)d_in[4];
    float* out = (float*)d_out;

    cvt_x_kernel<<<(M_TOT * K_TOT / 8) / 256, 256>>>((const float4*)x);
    deq_w_kernel<<<N_TOT, 256>>>(wd, ws, g);

    cudaFuncSetAttribute(gemm_kernel, cudaFuncAttributeMaxDynamicSharedMemorySize, SMEM_TOTAL);
    dim3 grid(N_TOT / BN, M_TOT / BM);   // (16, 64)
    gemm_kernel<<<grid, 256, SMEM_TOTAL>>>(bias, out);
}

// round 7
// speedup vs baseline: 1.0003x; 1.0003x over previous
#include <cuda_runtime.h>
#include <cuda_fp16.h>
#include <cstdint>
#include <cstddef>

#define DI __device__ __forceinline__

static constexpr int M_TOT = 8192, N_TOT = 4096, K_TOT = 4096;
static constexpr int BM = 256, BN = 128, BK = 64;
static constexpr int NSTG = 3;
static constexpr int NK = K_TOT / BK;                 // 64 chunks

static constexpr int A_STG = BM * 128;                // 32768 B
static constexpr int B_STG = BN * 128;                // 16384 B
static constexpr int STAGE_BYTES = A_STG + B_STG;     // 49152 B
static constexpr int SM_BIAS = 0;                     // 128 floats
static constexpr int SM_STAGE = 1024;
static constexpr int SMEM_TOTAL = SM_STAGE + NSTG * STAGE_BYTES;  // 148480

// scratch (allocation-free rule: __device__ globals)
__device__ uint4 g_x16_v[(size_t)M_TOT * K_TOT / 8];   // 64 MB fp16 x
__device__ uint4 g_w16_v[(size_t)N_TOT * K_TOT / 8];   // 32 MB fp16 W

// ------------------------- PTX helpers (sm_80+ baseline only) -------------------------
DI uint32_t smem_u32(const void* p) {
    uint32_t a;
    asm("{.reg .u64 t; cvta.to.shared.u64 t, %1; cvt.u32.u64 %0, t;}" : "=r"(a) : "l"(p));
    return a;
}
DI void cp16(uint32_t dst, const void* src) {
    asm volatile("cp.async.cg.shared.global [%0], [%1], 16;" :: "r"(dst), "l"(src));
}
DI void cp_commit() { asm volatile("cp.async.commit_group;" ::: "memory"); }
template <int N> DI void cp_wait() { asm volatile("cp.async.wait_group %0;" :: "n"(N) : "memory"); }

DI void ldsm_x4(uint32_t& r0, uint32_t& r1, uint32_t& r2, uint32_t& r3, uint32_t a) {
    asm volatile("ldmatrix.sync.aligned.m8n8.x4.shared.b16 {%0,%1,%2,%3}, [%4];"
                 : "=r"(r0), "=r"(r1), "=r"(r2), "=r"(r3) : "r"(a));
}
DI void mma16816(float* c, uint32_t a0, uint32_t a1, uint32_t a2, uint32_t a3,
                 uint32_t b0, uint32_t b1) {
    asm volatile(
        "mma.sync.aligned.m16n8k16.row.col.f32.f16.f16.f32 "
        "{%0,%1,%2,%3}, {%4,%5,%6,%7}, {%8,%9}, {%0,%1,%2,%3};"
        : "+f"(c[0]), "+f"(c[1]), "+f"(c[2]), "+f"(c[3])
        : "r"(a0), "r"(a1), "r"(a2), "r"(a3), "r"(b0), "r"(b1));
}
#define SWZ(row, colbyte) ((uint32_t)(colbyte) ^ (((uint32_t)(row) & 7u) << 4))

// ------------------------- pre-kernel 1: x fp32 -> fp16 -------------------------
__global__ void __launch_bounds__(256) cvt_x_kernel(const float4* __restrict__ x) {
    size_t i = (size_t)blockIdx.x * 256 + threadIdx.x;   // 8 floats per thread
    float4 a = x[2 * i], b = x[2 * i + 1];
    __half2* o = (__half2*)g_x16_v;
    o[4 * i + 0] = __floats2half2_rn(a.x, a.y);
    o[4 * i + 1] = __floats2half2_rn(a.z, a.w);
    o[4 * i + 2] = __floats2half2_rn(b.x, b.y);
    o[4 * i + 3] = __floats2half2_rn(b.z, b.w);
}

// ------------------------- pre-kernel 2: fp4 dequant -> fp16 W -------------------------
DI float fp4_val(uint32_t n) {
    uint32_t s = (n >> 3) & 1, e = (n >> 1) & 3, m = n & 1;
    uint32_t bits = e ? (((e + 126u) << 23) | (m << 22)) : (m ? 0x3F000000u : 0u);
    bits |= s << 31;
    return __uint_as_float(bits);
}

__global__ void __launch_bounds__(256) deq_w_kernel(const int* __restrict__ wd,
                                                    const int* __restrict__ ws,
                                                    const float* __restrict__ g) {
    int row = blockIdx.x;        // output row 0..4095
    int grp = threadIdx.x;       // scale group 0..255 (16 input cols each)
    float gl = *g;
    int code = ws[row * 256 + grp];            // e4m3 code
    int e = (code >> 3) & 0xF, mm = code & 7;
    float sc = e ? __uint_as_float(((uint32_t)(e + 120) << 23) | ((uint32_t)mm << 20))
                 : (float)mm * 0.001953125f;   // m * 2^-9 (subnormal)
    if (code & 0x80) sc = -sc;
    sc *= gl;

    const int4* src = (const int4*)(wd + (size_t)row * 2048 + grp * 8);
    int4 p0 = src[0], p1 = src[1];
    int v[8] = {p0.x, p0.y, p0.z, p0.w, p1.x, p1.y, p1.z, p1.w};
    __half2 o[8];
#pragma unroll
    for (int j = 0; j < 8; ++j) {
        uint32_t b = (uint32_t)v[j];
        o[j] = __floats2half2_rn(fp4_val(b & 0xF) * sc, fp4_val((b >> 4) & 0xF) * sc);
    }
    uint4* dst = (uint4*)((half*)g_w16_v + (size_t)row * 4096 + grp * 16);
    dst[0] = ((const uint4*)o)[0];
    dst[1] = ((const uint4*)o)[1];
}

// --------------- GEMM: mma.sync f16, 256x128 tile, 512 thr, 3-stage cp.async ----------
__global__ void __launch_bounds__(512, 1) gemm_kernel(const float* __restrict__ bias,
                                                      float* __restrict__ out) {
    extern __shared__ char smem[];
    const uint32_t sb = smem_u32(smem);
    const int tid = threadIdx.x, wid = tid >> 5, lane = tid & 31;
    const int wm = wid >> 2;          // 0..3  -> 64-row band
    const int wn = wid & 3;           // 0..3  -> 32-col band
    const int n0 = blockIdx.x * BN;
    const int m0 = blockIdx.y * BM;
    const half* X = (const half*)g_x16_v;
    const half* Wm = (const half*)g_w16_v;

    if (tid < BN) ((float*)(smem + SM_BIAS))[tid] = bias[n0 + tid];

    // stage loader: A rows = x[m0..+256], B rows = W[n0..+128]; 128B rows, XOR swizzle
    // 384 rows * 8 chunks of 16B = 3072 chunks; 512 threads -> 6 per thread
    auto load_stage = [&](int chunk) {
        const uint32_t st = sb + SM_STAGE + (uint32_t)(chunk % NSTG) * STAGE_BYTES;
        const int kc = chunk * BK;
#pragma unroll
        for (int j = 0; j < 6; ++j) {
            int c = tid + 512 * j;
            int row = c >> 3, col = c & 7;
            int isA = (row < BM);
            int lr = isA ? row : row - BM;
            const half* src = isA ? (X + (size_t)(m0 + lr) * K_TOT + kc + col * 8)
                                  : (Wm + (size_t)(n0 + lr) * K_TOT + kc + col * 8);
            uint32_t dst = st + (isA ? 0u : (uint32_t)A_STG)
                              + (uint32_t)lr * 128 + SWZ(lr, col * 16);
            cp16(dst, src);
        }
    };

    for (int c = 0; c < NSTG - 1; ++c) { load_stage(c); cp_commit(); }

    float acc[4][4][4];
#pragma unroll
    for (int mi = 0; mi < 4; ++mi)
#pragma unroll
        for (int ni = 0; ni < 4; ++ni)
#pragma unroll
            for (int q = 0; q < 4; ++q) acc[mi][ni][q] = 0.f;

#pragma unroll 1
    for (int ki = 0; ki < NK; ++ki) {
        cp_wait<NSTG - 2>();
        __syncthreads();
        if (ki + NSTG - 1 < NK) load_stage(ki + NSTG - 1);
        cp_commit();

        const uint32_t st = sb + SM_STAGE + (uint32_t)(ki % NSTG) * STAGE_BYTES;
        const uint32_t aS = st, bS = st + A_STG;
#pragma unroll
        for (int ks = 0; ks < 4; ++ks) {
            const int k0 = ks * 16;                    // halfs
            uint32_t af[4][4];
#pragma unroll
            for (int mi = 0; mi < 4; ++mi) {           // A frags: ldmatrix.x4 (rows = m)
                int row = wm * 64 + mi * 16 + (lane & 15);
                int colb = (k0 + ((lane >> 4) << 3)) * 2;
                ldsm_x4(af[mi][0], af[mi][1], af[mi][2], af[mi][3],
                        aS + (uint32_t)row * 128 + SWZ(row, colb));
            }
            uint32_t bf[4][2];
#pragma unroll
            for (int p = 0; p < 2; ++p) {              // B frags: NON-trans ldmatrix (rows = n)
                int row = wn * 32 + p * 16 + ((lane >> 4) << 3) + (lane & 7);
                int colb = (k0 + (((lane >> 3) & 1) << 3)) * 2;
                ldsm_x4(bf[2 * p][0], bf[2 * p][1], bf[2 * p + 1][0], bf[2 * p + 1][1],
                        bS + (uint32_t)row * 128 + SWZ(row, colb));
            }
#pragma unroll
            for (int mi = 0; mi < 4; ++mi)
#pragma unroll
                for (int ni = 0; ni < 4; ++ni)
                    mma16816(acc[mi][ni], af[mi][0], af[mi][1], af[mi][2], af[mi][3],
                             bf[ni][0], bf[ni][1]);
        }
    }
    cp_wait<0>();

    // epilogue: D m16n8 frag layout -> global + bias
    const float* sbias = (const float*)(smem + SM_BIAS);
#pragma unroll
    for (int mi = 0; mi < 4; ++mi) {
        int mr = m0 + wm * 64 + mi * 16 + (lane >> 2);
        float* o0 = out + (size_t)mr * N_TOT;
        float* o1 = out + (size_t)(mr + 8) * N_TOT;
#pragma unroll
        for (int ni = 0; ni < 4; ++ni) {
            int nc = wn * 32 + ni * 8 + (lane & 3) * 2;
            float b0 = sbias[nc], b1 = sbias[nc + 1];
            int ng = n0 + nc;
            *(float2*)(o0 + ng) = make_float2(acc[mi][ni][0] + b0, acc[mi][ni][1] + b1);
            *(float2*)(o1 + ng) = make_float2(acc[mi][ni][2] + b0, acc[mi][ni][3] + b1);
        }
    }
}

// ------------------------- launch -------------------------
extern "C" void kernel_launch(void* const* d_in, const int* in_sizes, int n_in,
                              void* d_out, int out_size) {
    const float* x  = (const float*)d_in[0];
    const int* wd   = (const int*)d_in[1];
    const int* ws   = (const int*)d_in[2];
    const float* g  = (const float*)d_in[3];
    const float* bias = (const float*)d_in[4];
    float* out = (float*)d_out;

    cvt_x_kernel<<<(M_TOT * K_TOT / 8) / 256, 256>>>((const float4*)x);
    deq_w_kernel<<<N_TOT, 256>>>(wd, ws, g);

    cudaFuncSetAttribute(gemm_kernel, cudaFuncAttributeMaxDynamicSharedMemorySize, SMEM_TOTAL);
    dim3 grid(N_TOT / BN, M_TOT / BM);   // (32, 32)
    gemm_kernel<<<grid, 512, SMEM_TOTAL>>>(bias, out);
}

// round 8
// speedup vs baseline: 1.0526x; 1.0523x over previous
#include <cuda_runtime.h>
#include <cuda_fp16.h>
#include <cstdint>
#include <cstddef>

#define DI __device__ __forceinline__

static constexpr int M_TOT = 8192, N_TOT = 4096, K_TOT = 4096;
static constexpr int BM = 128, BN = 128, BK = 64;
static constexpr int NSTG = 3;
static constexpr int NK = K_TOT / BK;                 // 64 chunks

static constexpr int A_STG = BM * 128;                // 16384 B
static constexpr int B_STG = BN * 128;                // 16384 B
static constexpr int STAGE_BYTES = A_STG + B_STG;     // 32768 B
static constexpr int SM_BIAS = 0;                     // 128 floats
static constexpr int SM_STAGE = 1024;
static constexpr int SMEM_TOTAL = SM_STAGE + NSTG * STAGE_BYTES;  // 99328 (x2 CTAs = 198656 < 227KB)

// scratch (allocation-free rule: __device__ globals)
__device__ uint4 g_x16_v[(size_t)M_TOT * K_TOT / 8];   // 64 MB fp16 x
__device__ uint4 g_w16_v[(size_t)N_TOT * K_TOT / 8];   // 32 MB fp16 W

// ------------------------- PTX helpers (sm_80+ baseline only) -------------------------
DI uint32_t smem_u32(const void* p) {
    uint32_t a;
    asm("{.reg .u64 t; cvta.to.shared.u64 t, %1; cvt.u32.u64 %0, t;}" : "=r"(a) : "l"(p));
    return a;
}
DI void cp16(uint32_t dst, const void* src) {
    asm volatile("cp.async.cg.shared.global [%0], [%1], 16;" :: "r"(dst), "l"(src));
}
DI void cp_commit() { asm volatile("cp.async.commit_group;" ::: "memory"); }
template <int N> DI void cp_wait() { asm volatile("cp.async.wait_group %0;" :: "n"(N) : "memory"); }

DI void ldsm_x4(uint32_t& r0, uint32_t& r1, uint32_t& r2, uint32_t& r3, uint32_t a) {
    asm volatile("ldmatrix.sync.aligned.m8n8.x4.shared.b16 {%0,%1,%2,%3}, [%4];"
                 : "=r"(r0), "=r"(r1), "=r"(r2), "=r"(r3) : "r"(a));
}
DI void mma16816(float* c, uint32_t a0, uint32_t a1, uint32_t a2, uint32_t a3,
                 uint32_t b0, uint32_t b1) {
    asm volatile(
        "mma.sync.aligned.m16n8k16.row.col.f32.f16.f16.f32 "
        "{%0,%1,%2,%3}, {%4,%5,%6,%7}, {%8,%9}, {%0,%1,%2,%3};"
        : "+f"(c[0]), "+f"(c[1]), "+f"(c[2]), "+f"(c[3])
        : "r"(a0), "r"(a1), "r"(a2), "r"(a3), "r"(b0), "r"(b1));
}
#define SWZ(row, colbyte) ((uint32_t)(colbyte) ^ (((uint32_t)(row) & 7u) << 4))

// ------------------------- pre-kernel 1: x fp32 -> fp16 -------------------------
__global__ void __launch_bounds__(256) cvt_x_kernel(const float4* __restrict__ x) {
    size_t i = (size_t)blockIdx.x * 256 + threadIdx.x;   // 8 floats per thread
    float4 a = x[2 * i], b = x[2 * i + 1];
    __half2* o = (__half2*)g_x16_v;
    o[4 * i + 0] = __floats2half2_rn(a.x, a.y);
    o[4 * i + 1] = __floats2half2_rn(a.z, a.w);
    o[4 * i + 2] = __floats2half2_rn(b.x, b.y);
    o[4 * i + 3] = __floats2half2_rn(b.z, b.w);
}

// ------------------------- pre-kernel 2: fp4 dequant -> fp16 W -------------------------
DI float fp4_val(uint32_t n) {
    uint32_t s = (n >> 3) & 1, e = (n >> 1) & 3, m = n & 1;
    uint32_t bits = e ? (((e + 126u) << 23) | (m << 22)) : (m ? 0x3F000000u : 0u);
    bits |= s << 31;
    return __uint_as_float(bits);
}

__global__ void __launch_bounds__(256) deq_w_kernel(const int* __restrict__ wd,
                                                    const int* __restrict__ ws,
                                                    const float* __restrict__ g) {
    int row = blockIdx.x;        // output row 0..4095
    int grp = threadIdx.x;       // scale group 0..255 (16 input cols each)
    float gl = *g;
    int code = ws[row * 256 + grp];            // e4m3 code
    int e = (code >> 3) & 0xF, mm = code & 7;
    float sc = e ? __uint_as_float(((uint32_t)(e + 120) << 23) | ((uint32_t)mm << 20))
                 : (float)mm * 0.001953125f;   // m * 2^-9 (subnormal)
    if (code & 0x80) sc = -sc;
    sc *= gl;

    const int4* src = (const int4*)(wd + (size_t)row * 2048 + grp * 8);
    int4 p0 = src[0], p1 = src[1];
    int v[8] = {p0.x, p0.y, p0.z, p0.w, p1.x, p1.y, p1.z, p1.w};
    __half2 o[8];
#pragma unroll
    for (int j = 0; j < 8; ++j) {
        uint32_t b = (uint32_t)v[j];
        o[j] = __floats2half2_rn(fp4_val(b & 0xF) * sc, fp4_val((b >> 4) & 0xF) * sc);
    }
    uint4* dst = (uint4*)((half*)g_w16_v + (size_t)row * 4096 + grp * 16);
    dst[0] = ((const uint4*)o)[0];
    dst[1] = ((const uint4*)o)[1];
}

// --------- GEMM: mma.sync f16, 128x128 tile, 256 thr, 3-stage cp.async, 2 CTAs/SM -----
__global__ void __launch_bounds__(256, 2) gemm_kernel(const float* __restrict__ bias,
                                                      float* __restrict__ out) {
    extern __shared__ char smem[];
    const uint32_t sb = smem_u32(smem);
    const int tid = threadIdx.x, wid = tid >> 5, lane = tid & 31;
    const int wm = wid >> 2;          // 0..1  -> 64-row band
    const int wn = wid & 3;           // 0..3  -> 32-col band
    const int n0 = blockIdx.x * BN;
    const int m0 = blockIdx.y * BM;
    const half* X = (const half*)g_x16_v;
    const half* Wm = (const half*)g_w16_v;

    if (tid < BN) ((float*)(smem + SM_BIAS))[tid] = bias[n0 + tid];

    // stage loader: 256 rows (128 A + 128 B) * 8 chunks of 16B = 2048; 256 thr -> 8 each
    auto load_stage = [&](int chunk) {
        const uint32_t st = sb + SM_STAGE + (uint32_t)(chunk % NSTG) * STAGE_BYTES;
        const int kc = chunk * BK;
#pragma unroll
        for (int j = 0; j < 8; ++j) {
            int c = tid + 256 * j;
            int row = c >> 3, col = c & 7;
            int isA = (row < BM);
            int lr = isA ? row : row - BM;
            const half* src = isA ? (X + (size_t)(m0 + lr) * K_TOT + kc + col * 8)
                                  : (Wm + (size_t)(n0 + lr) * K_TOT + kc + col * 8);
            uint32_t dst = st + (isA ? 0u : (uint32_t)A_STG)
                              + (uint32_t)lr * 128 + SWZ(lr, col * 16);
            cp16(dst, src);
        }
    };

    for (int c = 0; c < NSTG - 1; ++c) { load_stage(c); cp_commit(); }

    float acc[4][4][4];
#pragma unroll
    for (int mi = 0; mi < 4; ++mi)
#pragma unroll
        for (int ni = 0; ni < 4; ++ni)
#pragma unroll
            for (int q = 0; q < 4; ++q) acc[mi][ni][q] = 0.f;

#pragma unroll 1
    for (int ki = 0; ki < NK; ++ki) {
        cp_wait<NSTG - 2>();
        __syncthreads();
        if (ki + NSTG - 1 < NK) load_stage(ki + NSTG - 1);
        cp_commit();

        const uint32_t st = sb + SM_STAGE + (uint32_t)(ki % NSTG) * STAGE_BYTES;
        const uint32_t aS = st, bS = st + A_STG;
#pragma unroll
        for (int ks = 0; ks < 4; ++ks) {
            const int k0 = ks * 16;                    // halfs
            uint32_t af[4][4];
#pragma unroll
            for (int mi = 0; mi < 4; ++mi) {           // A frags: ldmatrix.x4 (rows = m)
                int row = wm * 64 + mi * 16 + (lane & 15);
                int colb = (k0 + ((lane >> 4) << 3)) * 2;
                ldsm_x4(af[mi][0], af[mi][1], af[mi][2], af[mi][3],
                        aS + (uint32_t)row * 128 + SWZ(row, colb));
            }
            uint32_t bf[4][2];
#pragma unroll
            for (int p = 0; p < 2; ++p) {              // B frags: NON-trans ldmatrix (rows = n)
                int row = wn * 32 + p * 16 + ((lane >> 4) << 3) + (lane & 7);
                int colb = (k0 + (((lane >> 3) & 1) << 3)) * 2;
                ldsm_x4(bf[2 * p][0], bf[2 * p][1], bf[2 * p + 1][0], bf[2 * p + 1][1],
                        bS + (uint32_t)row * 128 + SWZ(row, colb));
            }
#pragma unroll
            for (int mi = 0; mi < 4; ++mi)
#pragma unroll
                for (int ni = 0; ni < 4; ++ni)
                    mma16816(acc[mi][ni], af[mi][0], af[mi][1], af[mi][2], af[mi][3],
                             bf[ni][0], bf[ni][1]);
        }
    }
    cp_wait<0>();

    // epilogue: D m16n8 frag layout -> global + bias
    const float* sbias = (const float*)(smem + SM_BIAS);
#pragma unroll
    for (int mi = 0; mi < 4; ++mi) {
        int mr = m0 + wm * 64 + mi * 16 + (lane >> 2);
        float* o0 = out + (size_t)mr * N_TOT;
        float* o1 = out + (size_t)(mr + 8) * N_TOT;
#pragma unroll
        for (int ni = 0; ni < 4; ++ni) {
            int nc = wn * 32 + ni * 8 + (lane & 3) * 2;
            float b0 = sbias[nc], b1 = sbias[nc + 1];
            int ng = n0 + nc;
            *(float2*)(o0 + ng) = make_float2(acc[mi][ni][0] + b0, acc[mi][ni][1] + b1);
            *(float2*)(o1 + ng) = make_float2(acc[mi][ni][2] + b0, acc[mi][ni][3] + b1);
        }
    }
}

// ------------------------- launch -------------------------
extern "C" void kernel_launch(void* const* d_in, const int* in_sizes, int n_in,
                              void* d_out, int out_size) {
    const float* x  = (const float*)d_in[0];
    const int* wd   = (const int*)d_in[1];
    const int* ws   = (const int*)d_in[2];
    const float* g  = (const float*)d_in[3];
    const float* bias = (const float*)d_in[4];
    float* out = (float*)d_out;

    cvt_x_kernel<<<(M_TOT * K_TOT / 8) / 256, 256>>>((const float4*)x);
    deq_w_kernel<<<N_TOT, 256>>>(wd, ws, g);

    cudaFuncSetAttribute(gemm_kernel, cudaFuncAttributeMaxDynamicSharedMemorySize, SMEM_TOTAL);
    dim3 grid(N_TOT / BN, M_TOT / BM);   // (32, 64)
    gemm_kernel<<<grid, 256, SMEM_TOTAL>>>(bias, out);
}

// round 9
// speedup vs baseline: 1.0739x; 1.0202x over previous
#include <cuda_runtime.h>
#include <cuda_fp16.h>
#include <cstdint>
#include <cstddef>

#define DI __device__ __forceinline__

static constexpr int M_TOT = 8192, N_TOT = 4096, K_TOT = 4096;
static constexpr int BM = 128, BN = 128, BK = 64;
static constexpr int NSTG = 3;
static constexpr int NK = K_TOT / BK;                 // 64 chunks

static constexpr int A_STG = BM * 128;                // 16384 B
static constexpr int B_STG = BN * 128;                // 16384 B
static constexpr int STAGE_BYTES = A_STG + B_STG;     // 32768 B
static constexpr int SM_BIAS = 0;                     // 128 floats
static constexpr int SM_STAGE = 1024;
static constexpr int SMEM_TOTAL = SM_STAGE + NSTG * STAGE_BYTES;  // 99328; x2 CTAs fits 227KB

// scratch (allocation-free rule: __device__ globals)
__device__ uint4 g_x16_v[(size_t)M_TOT * K_TOT / 8];   // 64 MB fp16 x
__device__ uint4 g_w16_v[(size_t)N_TOT * K_TOT / 8];   // 32 MB fp16 W

// ------------------------- PTX helpers (sm_80+ baseline only) -------------------------
DI uint32_t smem_u32(const void* p) {
    uint32_t a;
    asm("{.reg .u64 t; cvta.to.shared.u64 t, %1; cvt.u32.u64 %0, t;}" : "=r"(a) : "l"(p));
    return a;
}
DI void cp16(uint32_t dst, const void* src) {
    asm volatile("cp.async.cg.shared.global [%0], [%1], 16;" :: "r"(dst), "l"(src));
}
DI void cp_commit() { asm volatile("cp.async.commit_group;" ::: "memory"); }
template <int N> DI void cp_wait() { asm volatile("cp.async.wait_group %0;" :: "n"(N) : "memory"); }

DI void ldsm_x4(uint32_t& r0, uint32_t& r1, uint32_t& r2, uint32_t& r3, uint32_t a) {
    asm volatile("ldmatrix.sync.aligned.m8n8.x4.shared.b16 {%0,%1,%2,%3}, [%4];"
                 : "=r"(r0), "=r"(r1), "=r"(r2), "=r"(r3) : "r"(a));
}
DI void mma16816(float* c, uint32_t a0, uint32_t a1, uint32_t a2, uint32_t a3,
                 uint32_t b0, uint32_t b1) {
    asm volatile(
        "mma.sync.aligned.m16n8k16.row.col.f32.f16.f16.f32 "
        "{%0,%1,%2,%3}, {%4,%5,%6,%7}, {%8,%9}, {%0,%1,%2,%3};"
        : "+f"(c[0]), "+f"(c[1]), "+f"(c[2]), "+f"(c[3])
        : "r"(a0), "r"(a1), "r"(a2), "r"(a3), "r"(b0), "r"(b1));
}
#define SWZ(row, colbyte) ((uint32_t)(colbyte) ^ (((uint32_t)(row) & 7u) << 4))

// ------------------------- pre-kernel 1: x fp32 -> fp16 -------------------------
__global__ void __launch_bounds__(256) cvt_x_kernel(const float4* __restrict__ x) {
    size_t i = (size_t)blockIdx.x * 256 + threadIdx.x;   // 8 floats per thread
    float4 a = x[2 * i], b = x[2 * i + 1];
    __half2* o = (__half2*)g_x16_v;
    o[4 * i + 0] = __floats2half2_rn(a.x, a.y);
    o[4 * i + 1] = __floats2half2_rn(a.z, a.w);
    o[4 * i + 2] = __floats2half2_rn(b.x, b.y);
    o[4 * i + 3] = __floats2half2_rn(b.z, b.w);
}

// ------------------------- pre-kernel 2: fp4 dequant -> fp16 W -------------------------
DI float fp4_val(uint32_t n) {
    uint32_t s = (n >> 3) & 1, e = (n >> 1) & 3, m = n & 1;
    uint32_t bits = e ? (((e + 126u) << 23) | (m << 22)) : (m ? 0x3F000000u : 0u);
    bits |= s << 31;
    return __uint_as_float(bits);
}

__global__ void __launch_bounds__(256) deq_w_kernel(const int* __restrict__ wd,
                                                    const int* __restrict__ ws,
                                                    const float* __restrict__ g) {
    int row = blockIdx.x;        // output row 0..4095
    int grp = threadIdx.x;       // scale group 0..255 (16 input cols each)
    float gl = *g;
    int code = ws[row * 256 + grp];            // e4m3 code
    int e = (code >> 3) & 0xF, mm = code & 7;
    float sc = e ? __uint_as_float(((uint32_t)(e + 120) << 23) | ((uint32_t)mm << 20))
                 : (float)mm * 0.001953125f;   // m * 2^-9 (subnormal)
    if (code & 0x80) sc = -sc;
    sc *= gl;

    const int4* src = (const int4*)(wd + (size_t)row * 2048 + grp * 8);
    int4 p0 = src[0], p1 = src[1];
    int v[8] = {p0.x, p0.y, p0.z, p0.w, p1.x, p1.y, p1.z, p1.w};
    __half2 o[8];
#pragma unroll
    for (int j = 0; j < 8; ++j) {
        uint32_t b = (uint32_t)v[j];
        o[j] = __floats2half2_rn(fp4_val(b & 0xF) * sc, fp4_val((b >> 4) & 0xF) * sc);
    }
    uint4* dst = (uint4*)((half*)g_w16_v + (size_t)row * 4096 + grp * 16);
    dst[0] = ((const uint4*)o)[0];
    dst[1] = ((const uint4*)o)[1];
}

// ----- GEMM: mma.sync f16, 128x128 tile, 4 warps (64x64 each), 3-stage, 2 CTAs/SM -----
__global__ void __launch_bounds__(128, 2) gemm_kernel(const float* __restrict__ bias,
                                                      float* __restrict__ out) {
    extern __shared__ char smem[];
    const uint32_t sb = smem_u32(smem);
    const int tid = threadIdx.x, wid = tid >> 5, lane = tid & 31;
    const int wm = wid >> 1;          // 0..1  -> 64-row band
    const int wn = wid & 1;           // 0..1  -> 64-col band
    const int n0 = blockIdx.x * BN;
    const int m0 = blockIdx.y * BM;
    const half* X = (const half*)g_x16_v;
    const half* Wm = (const half*)g_w16_v;

    ((float*)(smem + SM_BIAS))[tid] = bias[n0 + tid];

    // stage loader: 256 rows (128 A + 128 B) * 8 chunks of 16B = 2048; 128 thr -> 16 each
    auto load_stage = [&](int chunk) {
        const uint32_t st = sb + SM_STAGE + (uint32_t)(chunk % NSTG) * STAGE_BYTES;
        const int kc = chunk * BK;
#pragma unroll
        for (int j = 0; j < 16; ++j) {
            int c = tid + 128 * j;
            int row = c >> 3, col = c & 7;
            int isA = (row < BM);
            int lr = isA ? row : row - BM;
            const half* src = isA ? (X + (size_t)(m0 + lr) * K_TOT + kc + col * 8)
                                  : (Wm + (size_t)(n0 + lr) * K_TOT + kc + col * 8);
            uint32_t dst = st + (isA ? 0u : (uint32_t)A_STG)
                              + (uint32_t)lr * 128 + SWZ(lr, col * 16);
            cp16(dst, src);
        }
    };

    for (int c = 0; c < NSTG - 1; ++c) { load_stage(c); cp_commit(); }

    float acc[4][8][4];
#pragma unroll
    for (int mi = 0; mi < 4; ++mi)
#pragma unroll
        for (int ni = 0; ni < 8; ++ni)
#pragma unroll
            for (int q = 0; q < 4; ++q) acc[mi][ni][q] = 0.f;

#pragma unroll 1
    for (int ki = 0; ki < NK; ++ki) {
        cp_wait<NSTG - 2>();
        __syncthreads();
        if (ki + NSTG - 1 < NK) load_stage(ki + NSTG - 1);
        cp_commit();

        const uint32_t st = sb + SM_STAGE + (uint32_t)(ki % NSTG) * STAGE_BYTES;
        const uint32_t aS = st, bS = st + A_STG;
#pragma unroll
        for (int ks = 0; ks < 4; ++ks) {
            const int k0 = ks * 16;                    // halfs
            uint32_t af[4][4];
#pragma unroll
            for (int mi = 0; mi < 4; ++mi) {           // A frags: ldmatrix.x4 (rows = m)
                int row = wm * 64 + mi * 16 + (lane & 15);
                int colb = (k0 + ((lane >> 4) << 3)) * 2;
                ldsm_x4(af[mi][0], af[mi][1], af[mi][2], af[mi][3],
                        aS + (uint32_t)row * 128 + SWZ(row, colb));
            }
            uint32_t bf[8][2];
#pragma unroll
            for (int p = 0; p < 4; ++p) {              // B frags: NON-trans ldmatrix (rows = n)
                int row = wn * 64 + p * 16 + ((lane >> 4) << 3) + (lane & 7);
                int colb = (k0 + (((lane >> 3) & 1) << 3)) * 2;
                ldsm_x4(bf[2 * p][0], bf[2 * p][1], bf[2 * p + 1][0], bf[2 * p + 1][1],
                        bS + (uint32_t)row * 128 + SWZ(row, colb));
            }
#pragma unroll
            for (int mi = 0; mi < 4; ++mi)
#pragma unroll
                for (int ni = 0; ni < 8; ++ni)
                    mma16816(acc[mi][ni], af[mi][0], af[mi][1], af[mi][2], af[mi][3],
                             bf[ni][0], bf[ni][1]);
        }
    }
    cp_wait<0>();

    // epilogue: D m16n8 frag layout -> global + bias
    const float* sbias = (const float*)(smem + SM_BIAS);
#pragma unroll
    for (int mi = 0; mi < 4; ++mi) {
        int mr = m0 + wm * 64 + mi * 16 + (lane >> 2);
        float* o0 = out + (size_t)mr * N_TOT;
        float* o1 = out + (size_t)(mr + 8) * N_TOT;
#pragma unroll
        for (int ni = 0; ni < 8; ++ni) {
            int nc = wn * 64 + ni * 8 + (lane & 3) * 2;
            float b0 = sbias[nc], b1 = sbias[nc + 1];
            int ng = n0 + nc;
            *(float2*)(o0 + ng) = make_float2(acc[mi][ni][0] + b0, acc[mi][ni][1] + b1);
            *(float2*)(o1 + ng) = make_float2(acc[mi][ni][2] + b0, acc[mi][ni][3] + b1);
        }
    }
}

// ------------------------- launch -------------------------
extern "C" void kernel_launch(void* const* d_in, const int* in_sizes, int n_in,
                              void* d_out, int out_size) {
    const float* x  = (const float*)d_in[0];
    const int* wd   = (const int*)d_in[1];
    const int* ws   = (const int*)d_in[2];
    const float* g  = (const float*)d_in[3];
    const float* bias = (const float*)d_in[4];
    float* out = (float*)d_out;

    cvt_x_kernel<<<(M_TOT * K_TOT / 8) / 256, 256>>>((const float4*)x);
    deq_w_kernel<<<N_TOT, 256>>>(wd, ws, g);

    cudaFuncSetAttribute(gemm_kernel, cudaFuncAttributeMaxDynamicSharedMemorySize, SMEM_TOTAL);
    dim3 grid(N_TOT / BN, M_TOT / BM);   // (32, 64)
    gemm_kernel<<<grid, 128, SMEM_TOTAL>>>(bias, out);
}

// round 10
// speedup vs baseline: 1.1368x; 1.0586x over previous
#include <cuda_runtime.h>
#include <cuda_fp16.h>
#include <cstdint>
#include <cstddef>

#define DI __device__ __forceinline__

static constexpr int M_TOT = 8192, N_TOT = 4096, K_TOT = 4096;
static constexpr int BM = 128, BN = 128, BK = 64;
static constexpr int NSTG = 3;
static constexpr int NK = K_TOT / BK;                 // 64 chunks

static constexpr int A_STG = BM * 128;                // 16384 B
static constexpr int B_STG = BN * 128;                // 16384 B
static constexpr int STAGE_BYTES = A_STG + B_STG;     // 32768 B
static constexpr int SM_BIAS = 0;                     // 128 floats
static constexpr int SM_STAGE = 1024;
static constexpr int SMEM_TOTAL = SM_STAGE + NSTG * STAGE_BYTES;  // 99328; x2 CTAs fits 227KB

// scratch (allocation-free rule: __device__ globals)
__device__ uint4 g_x16_v[(size_t)M_TOT * K_TOT / 8];   // 64 MB fp16 x
__device__ uint4 g_w16_v[(size_t)N_TOT * K_TOT / 8];   // 32 MB fp16 W

// ------------------------- PTX helpers (sm_80+ baseline only) -------------------------
DI uint32_t smem_u32(const void* p) {
    uint32_t a;
    asm("{.reg .u64 t; cvta.to.shared.u64 t, %1; cvt.u32.u64 %0, t;}" : "=r"(a) : "l"(p));
    return a;
}
DI void cp16(uint32_t dst, const void* src) {
    asm volatile("cp.async.cg.shared.global [%0], [%1], 16;" :: "r"(dst), "l"(src));
}
DI void cp_commit() { asm volatile("cp.async.commit_group;" ::: "memory"); }
template <int N> DI void cp_wait() { asm volatile("cp.async.wait_group %0;" :: "n"(N) : "memory"); }

DI void ldsm_x4(uint32_t& r0, uint32_t& r1, uint32_t& r2, uint32_t& r3, uint32_t a) {
    asm volatile("ldmatrix.sync.aligned.m8n8.x4.shared.b16 {%0,%1,%2,%3}, [%4];"
                 : "=r"(r0), "=r"(r1), "=r"(r2), "=r"(r3) : "r"(a));
}
DI void mma16816(float* c, uint32_t a0, uint32_t a1, uint32_t a2, uint32_t a3,
                 uint32_t b0, uint32_t b1) {
    asm volatile(
        "mma.sync.aligned.m16n8k16.row.col.f32.f16.f16.f32 "
        "{%0,%1,%2,%3}, {%4,%5,%6,%7}, {%8,%9}, {%0,%1,%2,%3};"
        : "+f"(c[0]), "+f"(c[1]), "+f"(c[2]), "+f"(c[3])
        : "r"(a0), "r"(a1), "r"(a2), "r"(a3), "r"(b0), "r"(b1));
}
#define SWZ(row, colbyte) ((uint32_t)(colbyte) ^ (((uint32_t)(row) & 7u) << 4))

// ------------------- fused pre-kernel: x fp32->fp16  +  fp4 dequant ------------------
DI float fp4_val(uint32_t n) {
    uint32_t s = (n >> 3) & 1, e = (n >> 1) & 3, m = n & 1;
    uint32_t bits = e ? (((e + 126u) << 23) | (m << 22)) : (m ? 0x3F000000u : 0u);
    bits |= s << 31;
    return __uint_as_float(bits);
}

static constexpr int CVT_BLOCKS = (M_TOT * K_TOT / 8) / 256;   // 16384

__global__ void __launch_bounds__(256) prep_kernel(const float4* __restrict__ x,
                                                   const int* __restrict__ wd,
                                                   const int* __restrict__ ws,
                                                   const float* __restrict__ g) {
    if (blockIdx.x < CVT_BLOCKS) {
        size_t i = (size_t)blockIdx.x * 256 + threadIdx.x;   // 8 floats per thread
        float4 a = x[2 * i], b = x[2 * i + 1];
        __half2* o = (__half2*)g_x16_v;
        o[4 * i + 0] = __floats2half2_rn(a.x, a.y);
        o[4 * i + 1] = __floats2half2_rn(a.z, a.w);
        o[4 * i + 2] = __floats2half2_rn(b.x, b.y);
        o[4 * i + 3] = __floats2half2_rn(b.z, b.w);
    } else {
        int row = blockIdx.x - CVT_BLOCKS;   // 0..4095
        int grp = threadIdx.x;               // 0..255
        float gl = *g;
        int code = ws[row * 256 + grp];
        int e = (code >> 3) & 0xF, mm = code & 7;
        float sc = e ? __uint_as_float(((uint32_t)(e + 120) << 23) | ((uint32_t)mm << 20))
                     : (float)mm * 0.001953125f;
        if (code & 0x80) sc = -sc;
        sc *= gl;

        const int4* src = (const int4*)(wd + (size_t)row * 2048 + grp * 8);
        int4 p0 = src[0], p1 = src[1];
        int v[8] = {p0.x, p0.y, p0.z, p0.w, p1.x, p1.y, p1.z, p1.w};
        __half2 o[8];
#pragma unroll
        for (int j = 0; j < 8; ++j) {
            uint32_t b = (uint32_t)v[j];
            o[j] = __floats2half2_rn(fp4_val(b & 0xF) * sc, fp4_val((b >> 4) & 0xF) * sc);
        }
        uint4* dst = (uint4*)((half*)g_w16_v + (size_t)row * 4096 + grp * 16);
        dst[0] = ((const uint4*)o)[0];
        dst[1] = ((const uint4*)o)[1];
    }
}

// ----- GEMM: mma.sync f16, 128x128 tile, 4 warps (64x64 each), 3-stage, 2 CTAs/SM -----
__global__ void __launch_bounds__(128, 2) gemm_kernel(const float* __restrict__ bias,
                                                      float* __restrict__ out) {
    extern __shared__ char smem[];
    const uint32_t sb = smem_u32(smem);
    const int tid = threadIdx.x, wid = tid >> 5, lane = tid & 31;
    const int wm = wid >> 1;          // 0..1  -> 64-row band
    const int wn = wid & 1;           // 0..1  -> 64-col band
    const int n0 = blockIdx.x * BN;
    const int m0 = blockIdx.y * BM;
    const half* X = (const half*)g_x16_v;
    const half* Wm = (const half*)g_w16_v;

    ((float*)(smem + SM_BIAS))[tid] = bias[n0 + tid];

    // precomputed per-thread frag base offsets (swizzled addressing)
    const int a_row_l = (lane & 15);
    const int a_col_l = ((lane >> 4) << 3) * 2;      // bytes within k-halfword group
    const int b_row_l = ((lane >> 4) << 3) + (lane & 7);
    const int b_col_l = (((lane >> 3) & 1) << 3) * 2;

    auto load_stage = [&](int chunk) {
        const uint32_t st = sb + SM_STAGE + (uint32_t)(chunk % NSTG) * STAGE_BYTES;
        const int kc = chunk * BK;
#pragma unroll
        for (int j = 0; j < 16; ++j) {
            int c = tid + 128 * j;
            int row = c >> 3, col = c & 7;
            int isA = (row < BM);
            int lr = isA ? row : row - BM;
            const half* src = isA ? (X + (size_t)(m0 + lr) * K_TOT + kc + col * 8)
                                  : (Wm + (size_t)(n0 + lr) * K_TOT + kc + col * 8);
            uint32_t dst = st + (isA ? 0u : (uint32_t)A_STG)
                              + (uint32_t)lr * 128 + SWZ(lr, col * 16);
            cp16(dst, src);
        }
    };

    auto load_frags = [&](uint32_t aS, uint32_t bS, int ks,
                          uint32_t (*af)[4], uint32_t (*bfr)[2]) {
        const int k0b = ks * 32;                       // 16 halfs = 32 bytes
#pragma unroll
        for (int mi = 0; mi < 4; ++mi) {               // A frags (rows = m)
            int row = wm * 64 + mi * 16 + a_row_l;
            ldsm_x4(af[mi][0], af[mi][1], af[mi][2], af[mi][3],
                    aS + (uint32_t)row * 128 + SWZ(row, k0b + a_col_l));
        }
#pragma unroll
        for (int p = 0; p < 4; ++p) {                  // B frags: NON-trans (rows = n)
            int row = wn * 64 + p * 16 + b_row_l;
            ldsm_x4(bfr[2 * p][0], bfr[2 * p][1], bfr[2 * p + 1][0], bfr[2 * p + 1][1],
                    bS + (uint32_t)row * 128 + SWZ(row, k0b + b_col_l));
        }
    };

    for (int c = 0; c < NSTG - 1; ++c) { load_stage(c); cp_commit(); }

    float acc[4][8][4];
#pragma unroll
    for (int mi = 0; mi < 4; ++mi)
#pragma unroll
        for (int ni = 0; ni < 8; ++ni)
#pragma unroll
            for (int q = 0; q < 4; ++q) acc[mi][ni][q] = 0.f;

    uint32_t af[2][4][4], bf[2][8][2];

#pragma unroll 1
    for (int ki = 0; ki < NK; ++ki) {
        cp_wait<NSTG - 2>();
        __syncthreads();
        const uint32_t st = sb + SM_STAGE + (uint32_t)(ki % NSTG) * STAGE_BYTES;
        const uint32_t aS = st, bS = st + A_STG;

        load_frags(aS, bS, 0, af[0], bf[0]);           // frags first -> compute starts ASAP
        if (ki + NSTG - 1 < NK) load_stage(ki + NSTG - 1);
        cp_commit();

#pragma unroll
        for (int ks = 0; ks < 4; ++ks) {
            const int cur = ks & 1;
            if (ks < 3) load_frags(aS, bS, ks + 1, af[cur ^ 1], bf[cur ^ 1]);
#pragma unroll
            for (int mi = 0; mi < 4; ++mi)
#pragma unroll
                for (int ni = 0; ni < 8; ++ni)
                    mma16816(acc[mi][ni],
                             af[cur][mi][0], af[cur][mi][1], af[cur][mi][2], af[cur][mi][3],
                             bf[cur][ni][0], bf[cur][ni][1]);
        }
    }
    cp_wait<0>();

    // epilogue: D m16n8 frag layout -> global + bias
    const float* sbias = (const float*)(smem + SM_BIAS);
#pragma unroll
    for (int mi = 0; mi < 4; ++mi) {
        int mr = m0 + wm * 64 + mi * 16 + (lane >> 2);
        float* o0 = out + (size_t)mr * N_TOT;
        float* o1 = out + (size_t)(mr + 8) * N_TOT;
#pragma unroll
        for (int ni = 0; ni < 8; ++ni) {
            int nc = wn * 64 + ni * 8 + (lane & 3) * 2;
            float b0 = sbias[nc], b1 = sbias[nc + 1];
            int ng = n0 + nc;
            *(float2*)(o0 + ng) = make_float2(acc[mi][ni][0] + b0, acc[mi][ni][1] + b1);
            *(float2*)(o1 + ng) = make_float2(acc[mi][ni][2] + b0, acc[mi][ni][3] + b1);
        }
    }
}

// ------------------------- launch -------------------------
extern "C" void kernel_launch(void* const* d_in, const int* in_sizes, int n_in,
                              void* d_out, int out_size) {
    const float* x  = (const float*)d_in[0];
    const int* wd   = (const int*)d_in[1];
    const int* ws   = (const int*)d_in[2];
    const float* g  = (const float*)d_in[3];
    const float* bias = (const float*)d_in[4];
    float* out = (float*)d_out;

    prep_kernel<<<CVT_BLOCKS + N_TOT, 256>>>((const float4*)x, wd, ws, g);

    cudaFuncSetAttribute(gemm_kernel, cudaFuncAttributeMaxDynamicSharedMemorySize, SMEM_TOTAL);
    dim3 grid(N_TOT / BN, M_TOT / BM);   // (32, 64)
    gemm_kernel<<<grid, 128, SMEM_TOTAL>>>(bias, out);
}